// round 10
// baseline (speedup 1.0000x reference)
#include <cuda_runtime.h>
#include <math.h>
#include <stdint.h>

// Problem dims
constexpr int NB = 128;    // batch
constexpr int NL = 1024;   // seq len
constexpr int NE = 64;     // embed
constexpr int NH = 512;    // hidden
constexpr int NV = 96;     // vocab

// RNN cluster kernel config
constexpr int CS   = 8;          // CTAs per cluster
constexpr int RPC  = 8;          // batch rows per cluster
constexpr int NCL  = NB / RPC;   // 16 clusters
constexpr int GRNN = NCL * CS;   // 128 CTAs
constexpr int TRNN = 512;        // threads per CTA (one per output col)
constexpr int KS   = NH / CS;    // 64 k-values owned per CTA

// Dynamic SMEM (floats):
//   buf [2][CS][KS][RPC]  partial mailboxes, r-contiguous (v2 scatter)  8192
//   proj[NV][KS]          token projection slice                        6144
//   h   [RPC][KS]         local hidden slice                             512
//   tok [2][RPC]          ints
constexpr int SM_BUF  = 2 * CS * KS * RPC;
constexpr int SM_PROJ = NV * KS;
constexpr int SM_HH   = RPC * KS;
constexpr int RNN_SMEM_BYTES = (SM_BUF + SM_PROJ + SM_HH) * 4 + 2 * RPC * 4 + 16;

// Logits kernel config (persistent, 8 rows/warp)
constexpr int LG_GRID = 148;
constexpr int LG_TILE = 128;                   // rows per tile (16 warps x 8)
constexpr int LG_NTILES = NB * NL / LG_TILE;   // 1024
constexpr int SMEM_LOG_BYTES = (NH / 2) * NV * 8; // 196608 B (u64 pairs)

// Scratch (device global: allocation-free rule)
__device__ float g_hs[(size_t)NB * NL * NH];   // 256 MB: all h_t

// ---------------------------------------------------------------------------
// Helpers
// ---------------------------------------------------------------------------
__device__ __forceinline__ uint32_t smem_u32(const void* p) {
    return (uint32_t)__cvta_generic_to_shared(p);
}
__device__ __forceinline__ unsigned long long packf2(float lo, float hi) {
    return (unsigned long long)__float_as_uint(lo) |
           ((unsigned long long)__float_as_uint(hi) << 32);
}
__device__ __forceinline__ float f2lo(unsigned long long v) {
    return __uint_as_float((uint32_t)v);
}
__device__ __forceinline__ float f2hi(unsigned long long v) {
    return __uint_as_float((uint32_t)(v >> 32));
}
// Packed fp32x2 FMA (exact fp32 per lane)
#define FMA2(acc, a, b) \
    asm volatile("fma.rn.f32x2 %0, %1, %2, %0;" : "+l"(acc) : "l"(a), "l"(b))

#define CL_ARRIVE() asm volatile("barrier.cluster.arrive.aligned;" ::: "memory")
#define CL_WAIT()   asm volatile("barrier.cluster.wait.aligned;"   ::: "memory")

// ---------------------------------------------------------------------------
// Kernel 1: clustered recurrence with fused input projection.
// rnn3 skeleton (measured best) with ONE change: rows computed in PAIRS
// (2 rows x 2 FMA2 chains = 4 live accs) and scattered with a single
// st.shared::cluster.v2.f32 per pair -> remote packet count halved
// (4096 -> 2048 per CTA/step). Mailbox transposed to [pb][src][jl][r]
// (r contiguous). Reduce mapping rr=tid&7, rjl=tid>>3 keeps the 8 mailbox
// reads bank-conflict-free (bank = rjl*8+rr mod 32 covers all 32).
// ---------------------------------------------------------------------------
__global__ __launch_bounds__(TRNN, 1)
void rnn6_kernel(const void* __restrict__ xraw,
                 const float* __restrict__ h0,
                 const float* __restrict__ Whh,
                 const float* __restrict__ emb,
                 const float* __restrict__ Wxh,
                 const float* __restrict__ bh,
                 float* __restrict__ finalh) {
    extern __shared__ float sm[];
    float* buf   = sm;                       // [2][CS][KS][RPC]
    float* sproj = sm + SM_BUF;              // [NV][KS]
    float* sh    = sproj + SM_PROJ;          // [RPC][KS]
    int*   stok  = (int*)(sh + SM_HH);       // [2][RPC]

    const int tid     = threadIdx.x;
    const int rank    = blockIdx.x & (CS - 1);
    const int cl      = blockIdx.x >> 3;
    const int row0    = cl * RPC;
    const int colbase = rank * KS;
    const int j       = tid;            // global output column 0..511
    const int owner   = j >> 6;         // owning CTA rank of column j
    const int jl      = j & (KS - 1);
    const int rr      = tid & 7;        // reduce-phase row   (remapped)
    const int rjl     = tid >> 3;       // reduce-phase col-in-slice

    // Detect x dtype: int64 (odd int32 words all zero) vs int32.
    const int* xi = (const int*)xraw;
    bool is64 = true;
    for (int i = 1; i < 128; i += 2) {
        if (xi[i] != 0) { is64 = false; break; }
    }
    const long long* x64 = (const long long*)xraw;
    const int*       x32 = (const int*)xraw;

    // ---- fused proj: sproj[v][c] = bh[cb+c] + sum_e emb[v][e]*Wxh[e][cb+c]
    {
        float* semb = sm;            // [NV][NE]     6144 floats (scratch)
        float* swx  = sm + NV * NE;  // [NE][KS]     4096 floats (scratch)
        for (int i = tid; i < NV * NE; i += TRNN) semb[i] = emb[i];
        for (int i = tid; i < NE * KS; i += TRNN) {
            int e = i >> 6, c = i & (KS - 1);
            swx[i] = Wxh[e * NH + colbase + c];
        }
        __syncthreads();
        float pr[NV * KS / TRNN];   // 12 outputs per thread
        #pragma unroll
        for (int o = 0; o < NV * KS / TRNN; o++) {
            int idx = o * TRNN + tid;
            int v = idx >> 6, c = idx & (KS - 1);
            float acc = bh[colbase + c];
            #pragma unroll 8
            for (int e = 0; e < NE; e++) acc += semb[v * NE + e] * swx[e * KS + c];
            pr[o] = acc;
        }
        __syncthreads();
        #pragma unroll
        for (int o = 0; o < NV * KS / TRNN; o++) sproj[o * TRNN + tid] = pr[o];
    }

    // W_hh slice -> registers, packed (W[cb+2p][j], W[cb+2p+1][j])
    unsigned long long wreg[KS / 2];
    {
        const float* Wb = Whh + (size_t)colbase * NH + j;
        #pragma unroll
        for (int p = 0; p < KS / 2; p++) {
            wreg[p] = packf2(Wb[(size_t)(2 * p) * NH], Wb[(size_t)(2 * p + 1) * NH]);
        }
    }
    // h init (thread covers (rr, rjl)); tokens t=0
    sh[rr * KS + rjl] = h0[(size_t)(row0 + rr) * NH + colbase + rjl];
    if (tid < RPC) {
        size_t idx = (size_t)(row0 + tid) * NL;
        stok[tid] = is64 ? (int)x64[idx] : x32[idx];
    }
    __syncthreads();
    CL_ARRIVE(); CL_WAIT();   // cluster initialized

    // Remote strip base in owner CTA's mailbox for this thread's column:
    // buf[pb][src=rank][jl][r]; pb term added in-loop.
    uint32_t rstrip;
    {
        uint32_t lbase = smem_u32(buf);
        asm volatile("mapa.shared::cluster.u32 %0, %1, %2;"
                     : "=r"(rstrip) : "r"(lbase), "r"(owner));
        rstrip += (uint32_t)(((rank * KS) + jl) * RPC * 4);
    }
    constexpr uint32_t PB_STRIDE = (uint32_t)(CS * KS * RPC * 4);  // 16384

    float* gdst = g_hs + (size_t)(row0 + rr) * NL * NH + colbase + rjl;
    float hprev = 0.f;

    for (int t = 0; t < NL; t++) {
        const int pb = t & 1;
        const uint32_t ra = rstrip + (uint32_t)pb * PB_STRIDE;

        // ---- compute rows in pairs + immediate v2 scatter ----
        #pragma unroll 1
        for (int p = 0; p < RPC / 2; p++) {
            const int r0 = 2 * p, r1 = 2 * p + 1;
            unsigned long long a0 = 0ull, a1 = 0ull, b0 = 0ull, b1 = 0ull;
            #pragma unroll
            for (int p2 = 0; p2 < KS / 4; p2++) {
                ulonglong2 h0v = *(const ulonglong2*)&sh[r0 * KS + p2 * 4];
                ulonglong2 h1v = *(const ulonglong2*)&sh[r1 * KS + p2 * 4];
                FMA2(a0, wreg[2 * p2],     h0v.x);
                FMA2(a1, wreg[2 * p2 + 1], h0v.y);
                FMA2(b0, wreg[2 * p2],     h1v.x);
                FMA2(b1, wreg[2 * p2 + 1], h1v.y);
            }
            float v0 = (f2lo(a0) + f2hi(a0)) + (f2lo(a1) + f2hi(a1));
            float v1 = (f2lo(b0) + f2hi(b0)) + (f2lo(b1) + f2hi(b1));
            asm volatile("st.shared::cluster.v2.f32 [%0], {%1, %2};"
                         :: "r"(ra + (uint32_t)(r0 * 4)), "f"(v0), "f"(v1)
                         : "memory");
        }

        CL_ARRIVE();

        // deferred work while partials fly: previous h -> gmem, next token
        if (t > 0) gdst[(size_t)(t - 1) * NH] = hprev;
        int tok_next = 0;
        if (tid < RPC && t + 1 < NL) {
            size_t idx = (size_t)(row0 + tid) * NL + (t + 1);
            tok_next = is64 ? (int)x64[idx] : x32[idx];
        }

        CL_WAIT();

        // ---- reduce own (rr, rjl): 8 partials + proj + tanh ----
        {
            float s = 0.f;
            #pragma unroll
            for (int s8 = 0; s8 < CS; s8++)
                s += buf[((pb * CS + s8) * KS + rjl) * RPC + rr];
            s += sproj[stok[pb * RPC + rr] * KS + rjl];
            hprev = tanhf(s);
            sh[rr * KS + rjl] = hprev;
        }
        if (tid < RPC) stok[((t + 1) & 1) * RPC + tid] = tok_next;
        __syncthreads();
    }

    gdst[(size_t)(NL - 1) * NH] = hprev;
    if (finalh) finalh[(row0 + rr) * NH + colbase + rjl] = hprev;
}

// ---------------------------------------------------------------------------
// Kernel 2: persistent logits GEMM (unchanged: measured 352us).
// fc_w pre-packed u64 pairs in SMEM; hs as ulonglong2; 8 rows/warp.
// ---------------------------------------------------------------------------
__global__ __launch_bounds__(512, 1)
void logits3_kernel(const float* __restrict__ fcw,
                    const float* __restrict__ fcb,
                    float* __restrict__ out) {
    extern __shared__ unsigned long long spk[];  // [NH/2][NV] packed pairs
    const int tid  = threadIdx.x;
    const int lane = tid & 31;
    const int warp = tid >> 5;

    for (int i = tid; i < (NH / 2) * NV; i += 512) {
        int k2 = i / NV, c = i - k2 * NV;
        spk[i] = packf2(fcw[(2 * k2) * NV + c], fcw[(2 * k2 + 1) * NV + c]);
    }
    float b[3];
    #pragma unroll
    for (int g = 0; g < 3; g++) b[g] = fcb[g * 32 + lane];
    __syncthreads();

    for (int tile = blockIdx.x; tile < LG_NTILES; tile += gridDim.x) {
        const size_t row0 = (size_t)tile * LG_TILE + warp * 8;
        const float* hsr = g_hs + row0 * NH;

        unsigned long long acc[8][3];
        #pragma unroll
        for (int i = 0; i < 8; i++)
            #pragma unroll
            for (int g = 0; g < 3; g++) acc[i][g] = 0ull;

        for (int k4 = 0; k4 < NH / 4; k4++) {
            ulonglong2 hp[8];
            #pragma unroll
            for (int i = 0; i < 8; i++)
                hp[i] = *(const ulonglong2*)&hsr[(size_t)i * NH + 4 * k4];
            #pragma unroll
            for (int g = 0; g < 3; g++) {
                unsigned long long w0 = spk[(2 * k4) * NV + g * 32 + lane];
                unsigned long long w1 = spk[(2 * k4 + 1) * NV + g * 32 + lane];
                #pragma unroll
                for (int i = 0; i < 8; i++) {
                    FMA2(acc[i][g], hp[i].x, w0);
                    FMA2(acc[i][g], hp[i].y, w1);
                }
            }
        }
        #pragma unroll
        for (int i = 0; i < 8; i++)
            #pragma unroll
            for (int g = 0; g < 3; g++) {
                float s = f2lo(acc[i][g]) + f2hi(acc[i][g]) + b[g];
                out[(row0 + i) * NV + g * 32 + lane] = s;
            }
    }
}

// ---------------------------------------------------------------------------
// Launch
// ---------------------------------------------------------------------------
extern "C" void kernel_launch(void* const* d_in, const int* in_sizes, int n_in,
                              void* d_out, int out_size) {
    const void*  x      = d_in[0];                 // [B,L] int64 or int32
    const float* hidden = (const float*)d_in[1];   // [B,H]
    const float* emb    = (const float*)d_in[2];   // [V,E]
    const float* Wxh    = (const float*)d_in[3];   // [E,H]
    const float* Whh    = (const float*)d_in[4];   // [H,H]
    const float* bh     = (const float*)d_in[5];   // [H]
    const float* fcw    = (const float*)d_in[6];   // [H,V]
    const float* fcb    = (const float*)d_in[7];   // [V]

    float* out = (float*)d_out;                    // logits [B,L,V] ...
    const size_t logitsN = (size_t)NB * NL * NV;
    float* finalh = (out_size >= (int)(logitsN + (size_t)NB * NH))
                        ? out + logitsN : nullptr; // ... then final_h [B,H]

    cudaFuncSetAttribute(rnn6_kernel,
                         cudaFuncAttributeMaxDynamicSharedMemorySize,
                         RNN_SMEM_BYTES);
    cudaFuncSetAttribute(logits3_kernel,
                         cudaFuncAttributeMaxDynamicSharedMemorySize,
                         SMEM_LOG_BYTES);

    // Clustered recurrence (8-CTA clusters), proj fused into prologue
    {
        cudaLaunchConfig_t cfg = {};
        cfg.gridDim  = dim3(GRNN, 1, 1);
        cfg.blockDim = dim3(TRNN, 1, 1);
        cfg.dynamicSmemBytes = RNN_SMEM_BYTES;
        cfg.stream = 0;
        cudaLaunchAttribute attr[1];
        attr[0].id = cudaLaunchAttributeClusterDimension;
        attr[0].val.clusterDim.x = CS;
        attr[0].val.clusterDim.y = 1;
        attr[0].val.clusterDim.z = 1;
        cfg.attrs = attr;
        cfg.numAttrs = 1;
        cudaLaunchKernelEx(&cfg, rnn6_kernel, x, hidden, Whh, emb, Wxh, bh, finalh);
    }

    logits3_kernel<<<LG_GRID, 512, SMEM_LOG_BYTES>>>(fcw, fcb, out);
}

// round 11
// speedup vs baseline: 2.0102x; 2.0102x over previous
#include <cuda_runtime.h>
#include <math.h>
#include <stdint.h>

// Problem dims
constexpr int NB = 128;    // batch
constexpr int NL = 1024;   // seq len
constexpr int NE = 64;     // embed
constexpr int NH = 512;    // hidden
constexpr int NV = 96;     // vocab

// RNN kernel config (no clusters: L2 mailboxes + flags)
constexpr int CS   = 8;          // CTAs per group
constexpr int RPC  = 8;          // batch rows per group
constexpr int NCL  = NB / RPC;   // 16 groups
constexpr int GRNN = NCL * CS;   // 128 CTAs
constexpr int TRNN = 512;        // threads per CTA (one per output col)
constexpr int KS   = NH / CS;    // 64 k-values owned per CTA

// Dynamic SMEM (floats): prologue scratch needs NV*NE + NE*KS = 10240 floats;
// steady state needs sproj(6144) + sh(512) + tok.
constexpr int SM_PROJ = NV * KS;
constexpr int SM_HH   = RPC * KS;
constexpr int RNN_SMEM_BYTES = (NV * NE + NE * KS) * 4 + 256; // 41KB scratch max

// Logits kernel config (persistent, 8 rows/warp)
constexpr int LG_GRID = 148;
constexpr int LG_TILE = 128;                   // rows per tile (16 warps x 8)
constexpr int LG_NTILES = NB * NL / LG_TILE;   // 1024
constexpr int SMEM_LOG_BYTES = (NH / 2) * NV * 8; // 196608 B (u64 pairs)

// Scratch (device globals: allocation-free rule)
__device__ float g_hs[(size_t)NB * NL * NH];              // 256 MB: all h_t
__device__ float g_part[2 * NCL * CS * RPC * NH];         // 2 MB partial mailboxes
__device__ int   g_flag[2 * NCL * CS];                    // 256 flags (zero-init)

// ---------------------------------------------------------------------------
// Helpers
// ---------------------------------------------------------------------------
__device__ __forceinline__ unsigned long long packf2(float lo, float hi) {
    return (unsigned long long)__float_as_uint(lo) |
           ((unsigned long long)__float_as_uint(hi) << 32);
}
__device__ __forceinline__ float f2lo(unsigned long long v) {
    return __uint_as_float((uint32_t)v);
}
__device__ __forceinline__ float f2hi(unsigned long long v) {
    return __uint_as_float((uint32_t)(v >> 32));
}
// Packed fp32x2 FMA (exact fp32 per lane)
#define FMA2(acc, a, b) \
    asm volatile("fma.rn.f32x2 %0, %1, %2, %0;" : "+l"(acc) : "l"(a), "l"(b))

// ---------------------------------------------------------------------------
// Dummy kernel (ncu launch-index alignment: puts rnn7 at global launch #5).
// ---------------------------------------------------------------------------
__global__ void align_kernel() {}

// Flag reset for the NEXT call (graph replays reuse the flag array).
__global__ void clear_flags_kernel() { g_flag[threadIdx.x] = 0; }

// ---------------------------------------------------------------------------
// Kernel 1: recurrence with fused input projection — rnn3 hot-loop structure
// (measured best) ported from DSMEM clusters to L2 mailboxes:
//   producer: 8 coalesced scalar STG of partials -> __syncthreads ->
//             tid0: fence.acq_rel.gpu + st.relaxed flag = t+1
//   consumer: threads 0..7 spin ld.acquire.gpu on the 8 src flags,
//             __syncthreads, then 8 __ldcg partial reads + proj + tanh.
// Double-buffered mailboxes (pb = t&1); monotonic flags give t->t+2
// backpressure. Fully profilable (no clusters).
// ---------------------------------------------------------------------------
__global__ __launch_bounds__(TRNN, 1)
void rnn7_kernel(const void* __restrict__ xraw,
                 const float* __restrict__ h0,
                 const float* __restrict__ Whh,
                 const float* __restrict__ emb,
                 const float* __restrict__ Wxh,
                 const float* __restrict__ bh,
                 float* __restrict__ finalh) {
    extern __shared__ float sm[];
    float* sproj = sm;                       // [NV][KS]
    float* sh    = sm + SM_PROJ;             // [RPC][KS]
    int*   stok  = (int*)(sh + SM_HH);       // [2][RPC]

    const int tid     = threadIdx.x;
    const int rank    = blockIdx.x & (CS - 1);
    const int cl      = blockIdx.x >> 3;
    const int row0    = cl * RPC;
    const int colbase = rank * KS;
    const int j       = tid;            // global output column 0..511
    const int rr      = tid >> 6;       // reduce-phase row
    const int rjl     = tid & (KS - 1); // reduce-phase col-in-slice

    // Detect x dtype: int64 (odd int32 words all zero) vs int32.
    const int* xi = (const int*)xraw;
    bool is64 = true;
    for (int i = 1; i < 128; i += 2) {
        if (xi[i] != 0) { is64 = false; break; }
    }
    const long long* x64 = (const long long*)xraw;
    const int*       x32 = (const int*)xraw;

    // ---- fused proj: sproj[v][c] = bh[cb+c] + sum_e emb[v][e]*Wxh[e][cb+c]
    {
        float* semb = sm;            // [NV][NE]     6144 floats (scratch)
        float* swx  = sm + NV * NE;  // [NE][KS]     4096 floats (scratch)
        for (int i = tid; i < NV * NE; i += TRNN) semb[i] = emb[i];
        for (int i = tid; i < NE * KS; i += TRNN) {
            int e = i >> 6, c = i & (KS - 1);
            swx[i] = Wxh[e * NH + colbase + c];
        }
        __syncthreads();
        float pr[NV * KS / TRNN];   // 12 outputs per thread
        #pragma unroll
        for (int o = 0; o < NV * KS / TRNN; o++) {
            int idx = o * TRNN + tid;
            int v = idx >> 6, c = idx & (KS - 1);
            float acc = bh[colbase + c];
            #pragma unroll 8
            for (int e = 0; e < NE; e++) acc += semb[v * NE + e] * swx[e * KS + c];
            pr[o] = acc;
        }
        __syncthreads();
        #pragma unroll
        for (int o = 0; o < NV * KS / TRNN; o++) sproj[o * TRNN + tid] = pr[o];
    }

    // W_hh slice -> registers, packed (W[cb+2p][j], W[cb+2p+1][j])
    unsigned long long wreg[KS / 2];
    {
        const float* Wb = Whh + (size_t)colbase * NH + j;
        #pragma unroll
        for (int p = 0; p < KS / 2; p++) {
            wreg[p] = packf2(Wb[(size_t)(2 * p) * NH], Wb[(size_t)(2 * p + 1) * NH]);
        }
    }
    // h init; tokens t=0
    sh[tid] = h0[(size_t)(row0 + rr) * NH + colbase + rjl];
    if (tid < RPC) {
        size_t idx = (size_t)(row0 + tid) * NL;
        stok[tid] = is64 ? (int)x64[idx] : x32[idx];
    }
    __syncthreads();

    // Mailbox pointers. Layout: g_part[pb][cl][src][r][col(NH)]
    constexpr int PB_OFF = NCL * CS * RPC * NH;
    float* pbase = g_part + ((size_t)(cl * CS + rank) * RPC) * NH + j;  // producer
    const float* cbase = g_part + ((size_t)(cl * CS) * RPC + rr) * NH + colbase + rjl;
    int* fbase = g_flag + cl * CS;                                      // [src]
    int* fmine = fbase + rank;

    float* gdst = g_hs + (size_t)(row0 + rr) * NL * NH + colbase + rjl;
    float hprev = 0.f;

    for (int t = 0; t < NL; t++) {
        const int pb = t & 1;
        float* pdst = pbase + pb * PB_OFF;

        // ---- compute + immediate coalesced STG, one batch row at a time ----
        #pragma unroll 2
        for (int r = 0; r < RPC; r++) {
            unsigned long long a0 = 0ull, a1 = 0ull;
            #pragma unroll
            for (int p2 = 0; p2 < KS / 4; p2++) {
                ulonglong2 hh = *(const ulonglong2*)&sh[r * KS + p2 * 4];
                FMA2(a0, wreg[2 * p2],     hh.x);
                FMA2(a1, wreg[2 * p2 + 1], hh.y);
            }
            float v = (f2lo(a0) + f2hi(a0)) + (f2lo(a1) + f2hi(a1));
            __stcg(pdst + r * NH, v);
        }

        __syncthreads();   // all threads' partial stores issued

        // release: make partials visible, then post flag = t+1
        if (tid == 0) {
            asm volatile("fence.acq_rel.gpu;" ::: "memory");
            int* fp = g_flag + pb * NCL * CS + cl * CS + rank;
            asm volatile("st.relaxed.gpu.global.s32 [%0], %1;"
                         :: "l"(fp), "r"(t + 1) : "memory");
        }

        // deferred work while partials fly: previous h -> gmem, next token
        if (t > 0) gdst[(size_t)(t - 1) * NH] = hprev;
        int tok_next = 0;
        if (tid < RPC && t + 1 < NL) {
            size_t idx = (size_t)(row0 + tid) * NL + (t + 1);
            tok_next = is64 ? (int)x64[idx] : x32[idx];
        }

        // acquire: wait for all 8 src flags of this step
        if (tid < CS) {
            const int* fp = g_flag + pb * NCL * CS + cl * CS + tid;
            int v;
            do {
                asm volatile("ld.acquire.gpu.global.s32 %0, [%1];"
                             : "=r"(v) : "l"(fp) : "memory");
            } while (v < t + 1);
        }
        __syncthreads();

        // ---- reduce own column: 8 partials (L2) + proj + tanh ----
        {
            const float* c0 = cbase + pb * PB_OFF;
            float s = 0.f;
            #pragma unroll
            for (int s8 = 0; s8 < CS; s8++)
                s += __ldcg(c0 + (size_t)s8 * RPC * NH);
            s += sproj[stok[pb * RPC + rr] * KS + rjl];
            hprev = tanhf(s);
            sh[rr * KS + rjl] = hprev;
        }
        if (tid < RPC) stok[((t + 1) & 1) * RPC + tid] = tok_next;
        __syncthreads();
    }

    gdst[(size_t)(NL - 1) * NH] = hprev;
    if (finalh) finalh[(row0 + rr) * NH + colbase + rjl] = hprev;
}

// ---------------------------------------------------------------------------
// Kernel 2: persistent logits GEMM (unchanged: measured 352us).
// fc_w pre-packed u64 pairs in SMEM; hs as ulonglong2; 8 rows/warp.
// ---------------------------------------------------------------------------
__global__ __launch_bounds__(512, 1)
void logits3_kernel(const float* __restrict__ fcw,
                    const float* __restrict__ fcb,
                    float* __restrict__ out) {
    extern __shared__ unsigned long long spk[];  // [NH/2][NV] packed pairs
    const int tid  = threadIdx.x;
    const int lane = tid & 31;
    const int warp = tid >> 5;

    for (int i = tid; i < (NH / 2) * NV; i += 512) {
        int k2 = i / NV, c = i - k2 * NV;
        spk[i] = packf2(fcw[(2 * k2) * NV + c], fcw[(2 * k2 + 1) * NV + c]);
    }
    float b[3];
    #pragma unroll
    for (int g = 0; g < 3; g++) b[g] = fcb[g * 32 + lane];
    __syncthreads();

    for (int tile = blockIdx.x; tile < LG_NTILES; tile += gridDim.x) {
        const size_t row0 = (size_t)tile * LG_TILE + warp * 8;
        const float* hsr = g_hs + row0 * NH;

        unsigned long long acc[8][3];
        #pragma unroll
        for (int i = 0; i < 8; i++)
            #pragma unroll
            for (int g = 0; g < 3; g++) acc[i][g] = 0ull;

        for (int k4 = 0; k4 < NH / 4; k4++) {
            ulonglong2 hp[8];
            #pragma unroll
            for (int i = 0; i < 8; i++)
                hp[i] = *(const ulonglong2*)&hsr[(size_t)i * NH + 4 * k4];
            #pragma unroll
            for (int g = 0; g < 3; g++) {
                unsigned long long w0 = spk[(2 * k4) * NV + g * 32 + lane];
                unsigned long long w1 = spk[(2 * k4 + 1) * NV + g * 32 + lane];
                #pragma unroll
                for (int i = 0; i < 8; i++) {
                    FMA2(acc[i][g], hp[i].x, w0);
                    FMA2(acc[i][g], hp[i].y, w1);
                }
            }
        }
        #pragma unroll
        for (int i = 0; i < 8; i++)
            #pragma unroll
            for (int g = 0; g < 3; g++) {
                float s = f2lo(acc[i][g]) + f2hi(acc[i][g]) + b[g];
                out[(row0 + i) * NV + g * 32 + lane] = s;
            }
    }
}

// ---------------------------------------------------------------------------
// Launch: [align, rnn7, logits3, clear_flags] — rnn7 lands at launch #5 for
// ncu's "-s 5 -c 1". clear_flags resets the flag array for the next replay
// (first call uses the zero-initialized device global).
// ---------------------------------------------------------------------------
extern "C" void kernel_launch(void* const* d_in, const int* in_sizes, int n_in,
                              void* d_out, int out_size) {
    const void*  x      = d_in[0];                 // [B,L] int64 or int32
    const float* hidden = (const float*)d_in[1];   // [B,H]
    const float* emb    = (const float*)d_in[2];   // [V,E]
    const float* Wxh    = (const float*)d_in[3];   // [E,H]
    const float* Whh    = (const float*)d_in[4];   // [H,H]
    const float* bh     = (const float*)d_in[5];   // [H]
    const float* fcw    = (const float*)d_in[6];   // [H,V]
    const float* fcb    = (const float*)d_in[7];   // [V]

    float* out = (float*)d_out;                    // logits [B,L,V] ...
    const size_t logitsN = (size_t)NB * NL * NV;
    float* finalh = (out_size >= (int)(logitsN + (size_t)NB * NH))
                        ? out + logitsN : nullptr; // ... then final_h [B,H]

    cudaFuncSetAttribute(rnn7_kernel,
                         cudaFuncAttributeMaxDynamicSharedMemorySize,
                         RNN_SMEM_BYTES);
    cudaFuncSetAttribute(logits3_kernel,
                         cudaFuncAttributeMaxDynamicSharedMemorySize,
                         SMEM_LOG_BYTES);

    align_kernel<<<1, 32>>>();
    rnn7_kernel<<<GRNN, TRNN, RNN_SMEM_BYTES>>>(x, hidden, Whh, emb, Wxh, bh, finalh);
    logits3_kernel<<<LG_GRID, 512, SMEM_LOG_BYTES>>>(fcw, fcb, out);
    clear_flags_kernel<<<1, 2 * NCL * CS>>>();
}